// round 10
// baseline (speedup 1.0000x reference)
#include <cuda_runtime.h>
#include <cuda_bf16.h>

#define NUM_GRAPHS 256
#define EDGE_DIM   128
#define GLOBAL_DIM 256
#define LN_EPS     1e-5f
#define BLOCKS     592          // 148 SMs x 4 CTAs — exactly one wave
#define THREADS    256

// Scratch (allocation-free rule: __device__ globals).
// g_sums/g_counts zeroed at load and re-zeroed by the tail each replay.
// g_bar self-resets each replay; g_gen is a monotonic generation counter.
__device__ float    g_sums[NUM_GRAPHS * EDGE_DIM];
__device__ float    g_counts[NUM_GRAPHS];
__device__ unsigned g_bar = 0;
__device__ unsigned g_gen = 0;

__device__ __forceinline__ void l2_prefetch(const void* p) {
    asm volatile("prefetch.global.L2 [%0];" :: "l"(p));
}

// One kernel: segment-sum phase -> device-wide barrier -> fuse tail.
__global__ void __launch_bounds__(THREADS, 4) fused_kernel(
    const float4* __restrict__ edge4,   // [n_edges, 32] float4
    const int*    __restrict__ batch,   // [n_edges] int32, sorted
    const float*  __restrict__ W,       // [EDGE_DIM, GLOBAL_DIM]
    const float*  __restrict__ b,       // [GLOBAL_DIM]
    const float*  __restrict__ ln_w,    // [GLOBAL_DIM]
    const float*  __restrict__ ln_b,    // [GLOBAL_DIM]
    float*        __restrict__ out,     // [NUM_GRAPHS, GLOBAL_DIM]
    int n_edges, int chunk)
{
    // ---- read generation BEFORE any possibility of release ----
    __shared__ unsigned s_gen;
    if (threadIdx.x == 0) s_gen = atomicAdd(&g_gen, 0u);

    // ---- L2 prefetch of fuse-phase params (W survives the __ldcs stream) ----
    if (blockIdx.x < 8) {
        int idx = blockIdx.x * THREADS + threadIdx.x;    // 0..2047
        if (idx < 1024) {
            l2_prefetch(W + idx * 32);                   // 1024 x 128B = 128 KB
        } else if (idx < 1032) {
            l2_prefetch(b    + (idx - 1024) * 32);
        } else if (idx < 1040) {
            l2_prefetch(ln_w + (idx - 1032) * 32);
        } else if (idx < 1048) {
            l2_prefetch(ln_b + (idx - 1040) * 32);
        }
    }

    // ================= phase 1: segment sum (at HBM ceiling) =================
    {
        int warp = (blockIdx.x * THREADS + threadIdx.x) >> 5;
        int lane = threadIdx.x & 31;
        long long e0 = (long long)warp * chunk;
        long long e1 = e0 + chunk;
        if (e1 > n_edges) e1 = n_edges;

        if (e0 < e1) {
            int seg_last = batch[e1 - 1];
            long long e = e0;
            while (e < e1) {
                int seg = batch[e];
                long long end;
                if (seg == seg_last) {
                    end = e1;                       // common: rest of chunk is one run
                } else {
                    long long lo = e, hi = e1 - 1;  // batch[lo]==seg, batch[hi]!=seg
                    while (hi - lo > 1) {
                        long long mid = (lo + hi) >> 1;
                        if (batch[mid] == seg) lo = mid; else hi = mid;
                    }
                    end = hi;
                }

                float4 a0 = make_float4(0.f, 0.f, 0.f, 0.f);
                float4 a1 = make_float4(0.f, 0.f, 0.f, 0.f);
                const float4* p = edge4 + e * 32 + lane;
                long long n = end - e;
                long long i = 0;
                #pragma unroll 1
                for (; i + 8 <= n; i += 8) {
                    float4 v0 = __ldcs(p + (i + 0) * 32);
                    float4 v1 = __ldcs(p + (i + 1) * 32);
                    float4 v2 = __ldcs(p + (i + 2) * 32);
                    float4 v3 = __ldcs(p + (i + 3) * 32);
                    float4 v4 = __ldcs(p + (i + 4) * 32);
                    float4 v5 = __ldcs(p + (i + 5) * 32);
                    float4 v6 = __ldcs(p + (i + 6) * 32);
                    float4 v7 = __ldcs(p + (i + 7) * 32);
                    a0.x += v0.x + v1.x + v2.x + v3.x;
                    a0.y += v0.y + v1.y + v2.y + v3.y;
                    a0.z += v0.z + v1.z + v2.z + v3.z;
                    a0.w += v0.w + v1.w + v2.w + v3.w;
                    a1.x += v4.x + v5.x + v6.x + v7.x;
                    a1.y += v4.y + v5.y + v6.y + v7.y;
                    a1.z += v4.z + v5.z + v6.z + v7.z;
                    a1.w += v4.w + v5.w + v6.w + v7.w;
                }
                for (; i < n; i++) {
                    float4 v = __ldcs(p + i * 32);
                    a0.x += v.x; a0.y += v.y; a0.z += v.z; a0.w += v.w;
                }
                a0.x += a1.x; a0.y += a1.y; a0.z += a1.z; a0.w += a1.w;

                float* dst = &g_sums[seg * EDGE_DIM + lane * 4];
                atomicAdd(dst + 0, a0.x);
                atomicAdd(dst + 1, a0.y);
                atomicAdd(dst + 2, a0.z);
                atomicAdd(dst + 3, a0.w);
                if (lane == 0) atomicAdd(&g_counts[seg], (float)n);

                e = end;
            }
        }
    }

    // ================= device-wide barrier (single wave -> safe) =============
    __threadfence();
    __syncthreads();
    if (threadIdx.x == 0) {
        unsigned my_gen = s_gen;
        unsigned v = atomicAdd(&g_bar, 1);
        if (v == BLOCKS - 1) {
            atomicExch(&g_bar, 0);          // reset for next replay
            __threadfence();
            atomicAdd(&g_gen, 1);           // release
        } else {
            while (atomicAdd(&g_gen, 0u) == my_gen) __nanosleep(128);
        }
    }
    __syncthreads();
    __threadfence();

    // ================= phase 2: fuse tail (blocks 0..255, one graph each) ===
    if (blockIdx.x >= NUM_GRAPHS) return;

    __shared__ float u_s[EDGE_DIM];
    __shared__ float red[8];
    __shared__ float bc[2];

    int g = blockIdx.x;
    int t = threadIdx.x;

    if (t < EDGE_DIM) {
        float c = fmaxf(g_counts[g], 1.0f);   // L2-hot from atomics
        u_s[t] = g_sums[g * EDGE_DIM + t] / c;
    }
    __syncthreads();

    // reset scratch for the next replay (after all reads above)
    if (t < EDGE_DIM) g_sums[g * EDGE_DIM + t] = 0.0f;
    if (t == 0)       g_counts[g] = 0.0f;

    // matmul: column t, W is L2-hot; 4 accumulators for FMA ILP, full unroll for MLP
    float acc0 = b[t], acc1 = 0.f, acc2 = 0.f, acc3 = 0.f;
    #pragma unroll
    for (int k = 0; k < EDGE_DIM; k += 4) {
        acc0 = fmaf(u_s[k + 0], W[(k + 0) * GLOBAL_DIM + t], acc0);
        acc1 = fmaf(u_s[k + 1], W[(k + 1) * GLOBAL_DIM + t], acc1);
        acc2 = fmaf(u_s[k + 2], W[(k + 2) * GLOBAL_DIM + t], acc2);
        acc3 = fmaf(u_s[k + 3], W[(k + 3) * GLOBAL_DIM + t], acc3);
    }
    float a = (acc0 + acc1) + (acc2 + acc3);

    int wid = t >> 5, lane = t & 31;

    // pass 1: mean
    float sum = a;
    #pragma unroll
    for (int o = 16; o; o >>= 1) sum += __shfl_xor_sync(0xffffffffu, sum, o);
    if (lane == 0) red[wid] = sum;
    __syncthreads();
    if (t == 0) {
        float S = 0.f;
        #pragma unroll
        for (int w = 0; w < 8; w++) S += red[w];
        bc[0] = S / (float)GLOBAL_DIM;
    }
    __syncthreads();
    float mu = bc[0];

    // pass 2: variance
    float d  = a - mu;
    float sq = d * d;
    #pragma unroll
    for (int o = 16; o; o >>= 1) sq += __shfl_xor_sync(0xffffffffu, sq, o);
    if (lane == 0) red[wid] = sq;
    __syncthreads();
    if (t == 0) {
        float Q = 0.f;
        #pragma unroll
        for (int w = 0; w < 8; w++) Q += red[w];
        bc[1] = rsqrtf(Q / (float)GLOBAL_DIM + LN_EPS);
    }
    __syncthreads();
    float inv = bc[1];

    out[g * GLOBAL_DIM + t] = d * inv * ln_w[t] + ln_b[t];
}

extern "C" void kernel_launch(void* const* d_in, const int* in_sizes, int n_in,
                              void* d_out, int out_size) {
    const float* edge_attr = (const float*)d_in[0];
    const int*   batch     = (const int*)d_in[1];
    const float* W         = (const float*)d_in[2];
    const float* b         = (const float*)d_in[3];
    const float* ln_w      = (const float*)d_in[4];
    const float* ln_b      = (const float*)d_in[5];
    float*       out       = (float*)d_out;

    int n_edges = in_sizes[1];

    const int warps = BLOCKS * (THREADS / 32);   // 4736
    int chunk = (n_edges + warps - 1) / warps;
    if (chunk < 1) chunk = 1;

    fused_kernel<<<BLOCKS, THREADS>>>((const float4*)edge_attr, batch,
                                      W, b, ln_w, ln_b, out, n_edges, chunk);
}